// round 2
// baseline (speedup 1.0000x reference)
#include <cuda_runtime.h>
#include <stdint.h>

#define NN 50000
#define L1N 25000
#define L2N 12500
#define L3N 6250
#define EE 800000
#define HD 128
#define BNS 0.9999950000374997f

static inline int cdiv(int a, int b){ return (a + b - 1) / b; }

// ------------------------- device scratch (static, no allocs) -------------------------
__device__ float g_h0[(size_t)NN*HD];
__device__ float g_h1[(size_t)L1N*HD];
__device__ float g_h2[(size_t)L2N*HD];
__device__ float g_a [(size_t)NN*HD];
__device__ float g_w [(size_t)NN*HD];
__device__ float g_o [(size_t)NN*HD];
__device__ float g_ew0[EE];
__device__ int   g_srcl[3][EE];
__device__ int   g_dstl[3][EE];
__device__ float g_ewl[3][EE];
__device__ float g_deg[NN];
__device__ float g_dinv[NN];
__device__ float g_selfc[NN];
__device__ float g_s[NN];
__device__ unsigned g_u[NN];
__device__ int g_perm1[L1N];
__device__ int g_perm2[L2N];
__device__ int g_perm3[L3N];
__device__ int g_pos[NN];
__device__ unsigned g_hist[2048];
__device__ unsigned g_mn, g_mx;
__device__ unsigned g_prefix;
__device__ int g_krem;
__device__ unsigned g_thr;
__device__ int g_T;
__device__ float g_pn;
__device__ int g_bg[256], g_be[256];
__device__ float g_gsum[HD];

// ------------------------- helpers -------------------------
__device__ __forceinline__ unsigned fenc(float f){
    unsigned u = __float_as_uint(f);
    return (u & 0x80000000u) ? ~u : (u | 0x80000000u);
}
__device__ __forceinline__ float fdec(unsigned u){
    return __uint_as_float((u & 0x80000000u) ? (u ^ 0x80000000u) : ~u);
}

// ------------------------- init -------------------------
__global__ void k_init(){
    int i = blockIdx.x * blockDim.x + threadIdx.x;
    if (i < 2048) g_hist[i] = 0u;
    if (i == 0){ g_mn = 0xFFFFFFFFu; g_mx = 0u; }
}

// ------------------------- edge embedding + min/max -------------------------
__global__ void k_ew(const float* __restrict__ ea, const float* __restrict__ ww,
                     const float* __restrict__ wb){
    int e = blockIdx.x * blockDim.x + threadIdx.x;
    bool inb = e < EE;
    float acc = 0.f;
    if (inb){
        acc = wb[0];
        const float* a = ea + (size_t)e * 16;
        #pragma unroll
        for (int j = 0; j < 16; j++) acc += a[j] * ww[j];
        g_ew0[e] = acc;
    }
    unsigned em = inb ? fenc(acc) : 0xFFFFFFFFu;
    unsigned eM = inb ? fenc(acc) : 0u;
    __shared__ unsigned smn[256], smx[256];
    smn[threadIdx.x] = em; smx[threadIdx.x] = eM;
    __syncthreads();
    for (int s = 128; s > 0; s >>= 1){
        if (threadIdx.x < s){
            smn[threadIdx.x] = min(smn[threadIdx.x], smn[threadIdx.x + s]);
            smx[threadIdx.x] = max(smx[threadIdx.x], smx[threadIdx.x + s]);
        }
        __syncthreads();
    }
    if (threadIdx.x == 0){ atomicMin(&g_mn, smn[0]); atomicMax(&g_mx, smx[0]); }
}

__global__ void k_ewnorm(){
    int e = blockIdx.x * blockDim.x + threadIdx.x;
    if (e >= EE) return;
    float mn = fdec(g_mn), mx = fdec(g_mx);
    g_ew0[e] = (g_ew0[e] - mn) / ((mx - mn) + 1e-7f);
}

// ------------------------- elementwise -------------------------
__global__ void k_bn(const float* __restrict__ x, const float* __restrict__ g,
                     const float* __restrict__ b, float* __restrict__ y, int cnt){
    int i = blockIdx.x * blockDim.x + threadIdx.x;
    if (i >= cnt) return;
    int d = i & (HD - 1);
    y[i] = x[i] * (g[d] * BNS) + b[d];
}

__global__ void k_lrelu(float* __restrict__ x, int cnt){
    int i = blockIdx.x * blockDim.x + threadIdx.x;
    if (i >= cnt) return;
    float v = x[i];
    x[i] = v > 0.f ? v : 0.01f * v;
}

// ------------------------- GCN pieces -------------------------
__global__ void k_deg(const int* __restrict__ dst, const float* __restrict__ w){
    int e = blockIdx.x * blockDim.x + threadIdx.x;
    if (e >= EE) return;
    float we = w[e];
    if (we != 0.f) atomicAdd(&g_deg[dst[e]], we);
}

__global__ void k_dinv(int n, float fill){
    int i = blockIdx.x * blockDim.x + threadIdx.x;
    if (i >= n) return;
    float dg = g_deg[i] + fill;
    g_dinv[i]  = rsqrtf(dg);
    g_selfc[i] = fill / dg;
}

// C[n,128] = A[n,128] @ W[128,128]  (fp32 register-tiled)
__global__ void __launch_bounds__(256) k_mm(const float* __restrict__ A,
                                            const float* __restrict__ W,
                                            float* __restrict__ C, int n){
    __shared__ float As[32][65];
    __shared__ float Ws[32][128];
    int tid = threadIdx.x;
    int row0 = blockIdx.x * 64;
    int tcol = tid & 31;
    int trow = tid >> 5;
    float acc[8][4];
    #pragma unroll
    for (int r = 0; r < 8; r++)
        #pragma unroll
        for (int c = 0; c < 4; c++) acc[r][c] = 0.f;

    for (int k0 = 0; k0 < 128; k0 += 32){
        #pragma unroll
        for (int i = 0; i < 8; i++){
            int idx = tid + i * 256;      // 0..2047
            int r = idx >> 5;
            int kk = idx & 31;
            int grow = row0 + r;
            As[kk][r] = (grow < n) ? A[(size_t)grow * 128 + k0 + kk] : 0.f;
        }
        #pragma unroll
        for (int i = 0; i < 16; i++){
            int idx = tid + i * 256;      // 0..4095
            int kk = idx >> 7;
            int c = idx & 127;
            Ws[kk][c] = W[(size_t)(k0 + kk) * 128 + c];
        }
        __syncthreads();
        #pragma unroll
        for (int k = 0; k < 32; k++){
            float b0 = Ws[k][tcol*4+0], b1 = Ws[k][tcol*4+1];
            float b2 = Ws[k][tcol*4+2], b3 = Ws[k][tcol*4+3];
            #pragma unroll
            for (int r = 0; r < 8; r++){
                float a = As[k][trow*8 + r];
                acc[r][0] += a * b0; acc[r][1] += a * b1;
                acc[r][2] += a * b2; acc[r][3] += a * b3;
            }
        }
        __syncthreads();
    }
    #pragma unroll
    for (int r = 0; r < 8; r++){
        int grow = row0 + trow*8 + r;
        if (grow < n){
            float4 v = make_float4(acc[r][0], acc[r][1], acc[r][2], acc[r][3]);
            *(float4*)&C[(size_t)grow * 128 + tcol * 4] = v;
        }
    }
}

__global__ void k_initout(const float* __restrict__ hp, const float* __restrict__ b,
                          float* __restrict__ out, int n){
    int i = blockIdx.x * blockDim.x + threadIdx.x;
    if (i >= n * HD) return;
    int row = i >> 7;
    int d = i & (HD - 1);
    out[i] = g_selfc[row] * hp[i] + b[d];
}

__global__ void k_scatter(const int* __restrict__ src, const int* __restrict__ dst,
                          const float* __restrict__ w, const float* __restrict__ hp,
                          float* __restrict__ out){
    int idx = blockIdx.x * blockDim.x + threadIdx.x;
    int e = idx >> 5;
    if (e >= EE) return;
    float we = __ldg(&w[e]);
    if (we == 0.f) return;
    int lane = threadIdx.x & 31;
    int s = src[e], d = dst[e];
    float c = g_dinv[s] * we * g_dinv[d];
    float4 v = *(const float4*)(hp + (size_t)s * 128 + lane * 4);
    float r0 = v.x * c, r1 = v.y * c, r2 = v.z * c, r3 = v.w * c;
    float* addr = out + (size_t)d * 128 + lane * 4;
    asm volatile("red.global.add.v4.f32 [%0], {%1, %2, %3, %4};"
                 :: "l"(addr), "f"(r0), "f"(r1), "f"(r2), "f"(r3) : "memory");
}

// ------------------------- TopK pooling -------------------------
__global__ void k_pnorm(const float* __restrict__ p, int k){
    int lane = threadIdx.x;
    float4 v = *(const float4*)(p + lane * 4);
    float s = v.x*v.x + v.y*v.y + v.z*v.z + v.w*v.w;
    #pragma unroll
    for (int o = 16; o > 0; o >>= 1) s += __shfl_xor_sync(0xffffffffu, s, o);
    if (lane == 0){ g_pn = sqrtf(s); g_krem = k; }
}

__global__ void k_score(const float* __restrict__ h, const float* __restrict__ p, int n){
    int wid = (blockIdx.x * blockDim.x + threadIdx.x) >> 5;
    int lane = threadIdx.x & 31;
    if (wid >= n) return;
    float4 hv = *(const float4*)(h + (size_t)wid * 128 + lane * 4);
    float4 pv = *(const float4*)(p + lane * 4);
    float d = hv.x*pv.x + hv.y*pv.y + hv.z*pv.z + hv.w*pv.w;
    #pragma unroll
    for (int o = 16; o > 0; o >>= 1) d += __shfl_xor_sync(0xffffffffu, d, o);
    if (lane == 0){
        float v = tanhf(d / g_pn);
        g_s[wid] = v;
        g_u[wid] = fenc(v);
    }
}

__global__ void k_hist(int n, int pass){
    __shared__ unsigned sh[2048];
    for (int j = threadIdx.x; j < 2048; j += blockDim.x) sh[j] = 0u;
    __syncthreads();
    unsigned pref = g_prefix;
    for (int i = blockIdx.x * blockDim.x + threadIdx.x; i < n; i += gridDim.x * blockDim.x){
        unsigned ui = g_u[i];
        if (pass == 0) atomicAdd(&sh[ui >> 21], 1u);
        else if (pass == 1){ if ((ui >> 21) == pref) atomicAdd(&sh[(ui >> 10) & 2047u], 1u); }
        else            { if ((ui >> 10) == pref) atomicAdd(&sh[ui & 1023u], 1u); }
    }
    __syncthreads();
    for (int j = threadIdx.x; j < 2048; j += blockDim.x){
        unsigned c = sh[j];
        if (c) atomicAdd(&g_hist[j], c);
    }
}

__global__ void k_select(int pass){
    int lane = threadIdx.x;
    int nbins = (pass < 2) ? 2048 : 1024;
    int chunk = nbins >> 5;
    int k = g_krem;
    int base = nbins - 1 - lane * chunk;
    unsigned cnt = 0;
    for (int j = 0; j < chunk; j++) cnt += g_hist[base - j];
    unsigned pre = cnt;
    #pragma unroll
    for (int off = 1; off < 32; off <<= 1){
        unsigned t = __shfl_up_sync(0xffffffffu, pre, off);
        if (lane >= off) pre += t;
    }
    pre -= cnt;
    bool sel = (pre < (unsigned)k) && ((unsigned)k <= pre + cnt);
    unsigned m = __ballot_sync(0xffffffffu, sel);
    int L = __ffs(m) - 1;
    if (lane == L){
        unsigned run = pre;
        for (int j = 0; j < chunk; j++){
            int bidx = base - j;
            unsigned c = g_hist[bidx];
            if (run + c >= (unsigned)k){
                if (pass == 0)      g_prefix = (unsigned)bidx;
                else if (pass == 1) g_prefix = (g_prefix << 11) | (unsigned)bidx;
                else { g_thr = (g_prefix << 10) | (unsigned)bidx; g_T = k - (int)run; }
                g_krem = k - (int)run;
                break;
            }
            run += c;
        }
    }
    __syncwarp();
    for (int j = lane; j < 2048; j += 32) g_hist[j] = 0u;
}

__global__ void k_c1(int n){
    int i = blockIdx.x * blockDim.x + threadIdx.x;
    bool inb = i < n;
    unsigned ut = g_thr;
    unsigned ui = inb ? g_u[i] : 0u;
    bool gt = inb && ui > ut;
    bool eq = inb && ui == ut;
    unsigned bg = __ballot_sync(0xffffffffu, gt);
    unsigned be = __ballot_sync(0xffffffffu, eq);
    __shared__ int wg[8], wqe[8];
    int w = threadIdx.x >> 5, lane = threadIdx.x & 31;
    if (lane == 0){ wg[w] = __popc(bg); wqe[w] = __popc(be); }
    __syncthreads();
    if (threadIdx.x == 0){
        int sg = 0, se = 0;
        for (int j = 0; j < 8; j++){ sg += wg[j]; se += wqe[j]; }
        g_bg[blockIdx.x] = sg; g_be[blockIdx.x] = se;
    }
}

__global__ void k_c2(int nb){
    int ag = 0, ae = 0;
    for (int b = 0; b < nb; b++){
        int tg = g_bg[b]; g_bg[b] = ag; ag += tg;
        int te = g_be[b]; g_be[b] = ae; ae += te;
    }
}

__global__ void k_c3(int n, int* __restrict__ perm){
    int i = blockIdx.x * blockDim.x + threadIdx.x;
    bool inb = i < n;
    unsigned ut = g_thr;
    int T = g_T;
    unsigned ui = inb ? g_u[i] : 0u;
    bool gt = inb && ui > ut;
    bool eq = inb && ui == ut;
    unsigned bg = __ballot_sync(0xffffffffu, gt);
    unsigned be = __ballot_sync(0xffffffffu, eq);
    int w = threadIdx.x >> 5, lane = threadIdx.x & 31;
    unsigned lm = (1u << lane) - 1u;
    int lgt = __popc(bg & lm), leq = __popc(be & lm);
    __shared__ int wg[8], wqe[8];
    if (lane == 0){ wg[w] = __popc(bg); wqe[w] = __popc(be); }
    __syncthreads();
    int wgp = 0, wep = 0;
    for (int j = 0; j < w; j++){ wgp += wg[j]; wep += wqe[j]; }
    if (inb){
        int gtB = g_bg[blockIdx.x] + wgp + lgt;
        int eqB = g_be[blockIdx.x] + wep + leq;
        int p = -1;
        if (gt) p = gtB + min(eqB, T);
        else if (eq && eqB < T) p = gtB + eqB;
        g_pos[i] = p;
        if (p >= 0) perm[p] = i;
    }
}

__global__ void k_relabel(const int* __restrict__ s, const int* __restrict__ d,
                          const float* __restrict__ w, int* __restrict__ ns,
                          int* __restrict__ nd, float* __restrict__ nw){
    int e = blockIdx.x * blockDim.x + threadIdx.x;
    if (e >= EE) return;
    int a = g_pos[s[e]], b = g_pos[d[e]];
    bool v = (a >= 0) && (b >= 0);
    ns[e] = v ? a : 0;
    nd[e] = v ? b : 0;
    nw[e] = v ? w[e] : 0.f;
}

// pooled + BN fused: out[new] = h[old]*score[old] * (gn*BNS) + bn
__global__ void k_pool(const float* __restrict__ h, const int* __restrict__ perm,
                       const float* __restrict__ gn, const float* __restrict__ bn,
                       float* __restrict__ out){
    int r = blockIdx.x, d = threadIdx.x;
    int old = perm[r];
    float v = g_s[old];
    out[(size_t)r * HD + d] = h[(size_t)old * HD + d] * v * (gn[d] * BNS) + bn[d];
}

__global__ void k_unpool(float* __restrict__ a, const int* __restrict__ perm,
                         const float* __restrict__ u){
    int r = blockIdx.x, d = threadIdx.x;
    int row = perm[r];
    a[(size_t)row * HD + d] += u[(size_t)r * HD + d];
}

// ------------------------- readout -------------------------
__global__ void k_colsum(const float* __restrict__ h, int n){
    int d = threadIdx.x;
    int r0 = blockIdx.x * 256;
    int rend = min(r0 + 256, n);
    float acc = 0.f;
    for (int r = r0; r < rend; r++) acc += h[(size_t)r * HD + d];
    atomicAdd(&g_gsum[d], acc);
}

__global__ void k_final(const float* __restrict__ Wr, const float* __restrict__ br,
                        const float* __restrict__ gr, const float* __restrict__ brn,
                        float* __restrict__ out, int osz){
    __shared__ float gs[HD];
    int t = threadIdx.x;
    gs[t] = g_gsum[t];
    __syncthreads();
    float acc = br[t];
    for (int d2 = 0; d2 < HD; d2++) acc += gs[d2] * Wr[d2 * HD + t];
    float r = acc * (gr[t] * BNS) + brn[t];
    if (t < osz) out[t] = r;
}

// ------------------------- host orchestration -------------------------
static void run_gcn(const int* src, const int* dst, const float* w, const float* in,
                    const float* W, const float* b, float fill, float* out, int n,
                    float* wbuf, void* degAddr){
    cudaMemsetAsync(degAddr, 0, (size_t)n * sizeof(float));
    k_deg<<<cdiv(EE, 256), 256>>>(dst, w);
    k_dinv<<<cdiv(n, 256), 256>>>(n, fill);
    k_mm<<<cdiv(n, 64), 256>>>(in, W, wbuf, n);
    k_initout<<<cdiv(n * HD, 256), 256>>>(wbuf, b, out, n);
    k_scatter<<<cdiv(EE * 32, 256), 256>>>(src, dst, w, wbuf, out);
}

static void run_pool(const float* h, int n, int k, const float* p, int* perm,
                     const int* src, const int* dst, const float* w,
                     int* nsrc, int* ndst, float* nw,
                     const float* gnp, const float* bnp, float* outp){
    k_pnorm<<<1, 32>>>(p, k);
    k_score<<<cdiv(n, 8), 256>>>(h, p, n);
    for (int pass = 0; pass < 3; pass++){
        k_hist<<<120, 256>>>(n, pass);
        k_select<<<1, 32>>>(pass);
    }
    int nb = cdiv(n, 256);
    k_c1<<<nb, 256>>>(n);
    k_c2<<<1, 1>>>(nb);
    k_c3<<<nb, 256>>>(n, perm);
    k_relabel<<<cdiv(EE, 256), 256>>>(src, dst, w, nsrc, ndst, nw);
    k_pool<<<k, HD>>>(h, perm, gnp, bnp, outp);
}

extern "C" void kernel_launch(void* const* d_in, const int* in_sizes, int n_in,
                              void* d_out, int out_size){
    const float* x   = (const float*)d_in[0];
    const int*   ei  = (const int*)d_in[1];
    const float* ea  = (const float*)d_in[2];
    const float* Wew = (const float*)d_in[3];
    const float* Web = (const float*)d_in[4];
    const float* Wd  = (const float*)d_in[5];
    const float* bd  = (const float*)d_in[6];
    const float* Wp  = (const float*)d_in[7];
    const float* Wu  = (const float*)d_in[8];
    const float* bu  = (const float*)d_in[9];
    const float* gn  = (const float*)d_in[10];
    const float* bnm = (const float*)d_in[11];
    const float* Wr  = (const float*)d_in[12];
    const float* br  = (const float*)d_in[13];
    const float* gr  = (const float*)d_in[14];
    const float* brn = (const float*)d_in[15];
    float* out = (float*)d_out;

    void *pH0, *pH1, *pH2, *pA, *pW, *pO, *pEw0, *pSrc, *pDst, *pEwl;
    void *pP1, *pP2, *pP3, *pDeg, *pGs;
    cudaGetSymbolAddress(&pH0, g_h0);
    cudaGetSymbolAddress(&pH1, g_h1);
    cudaGetSymbolAddress(&pH2, g_h2);
    cudaGetSymbolAddress(&pA, g_a);
    cudaGetSymbolAddress(&pW, g_w);
    cudaGetSymbolAddress(&pO, g_o);
    cudaGetSymbolAddress(&pEw0, g_ew0);
    cudaGetSymbolAddress(&pSrc, g_srcl);
    cudaGetSymbolAddress(&pDst, g_dstl);
    cudaGetSymbolAddress(&pEwl, g_ewl);
    cudaGetSymbolAddress(&pP1, g_perm1);
    cudaGetSymbolAddress(&pP2, g_perm2);
    cudaGetSymbolAddress(&pP3, g_perm3);
    cudaGetSymbolAddress(&pDeg, g_deg);
    cudaGetSymbolAddress(&pGs, g_gsum);

    float* h0 = (float*)pH0; float* h1 = (float*)pH1; float* h2 = (float*)pH2;
    float* a  = (float*)pA;  float* wb = (float*)pW;  float* o  = (float*)pO;
    float* ew0 = (float*)pEw0;
    int* srcB = (int*)pSrc; int* dstB = (int*)pDst; float* ewB = (float*)pEwl;
    int* src1 = srcB;        int* dst1 = dstB;        float* ew1 = ewB;
    int* src2 = srcB + EE;   int* dst2 = dstB + EE;   float* ew2 = ewB + EE;
    int* src3 = srcB + 2*EE; int* dst3 = dstB + 2*EE; float* ew3 = ewB + 2*EE;
    int* perm1 = (int*)pP1; int* perm2 = (int*)pP2; int* perm3 = (int*)pP3;
    const int* src0 = ei;
    const int* dst0 = ei + EE;

    // ---- edge embedding + normalization ----
    k_init<<<8, 256>>>();
    k_ew<<<cdiv(EE, 256), 256>>>(ea, Wew, Web);
    k_ewnorm<<<cdiv(EE, 256), 256>>>();

    // ---- BN0 + first GCN + lrelu -> h0 (xs[0]) ----
    k_bn<<<cdiv(NN * HD, 256), 256>>>(x, gn, bnm, a, NN * HD);
    run_gcn(src0, dst0, ew0, a, Wd, bd, 1.f, h0, NN, wb, pDeg);
    k_lrelu<<<cdiv(NN * HD, 256), 256>>>(h0, NN * HD);

    // ---- down: pool1 + GCN1 -> h1 ----
    run_pool(h0, NN, L1N, Wp, perm1, src0, dst0, ew0,
             src1, dst1, ew1, gn + HD, bnm + HD, a);
    run_gcn(src1, dst1, ew1, a, Wd + HD*HD, bd + HD, 1.f, h1, L1N, wb, pDeg);
    k_lrelu<<<cdiv(L1N * HD, 256), 256>>>(h1, L1N * HD);

    // ---- down: pool2 + GCN2 -> h2 ----
    run_pool(h1, L1N, L2N, Wp + HD, perm2, src1, dst1, ew1,
             src2, dst2, ew2, gn + 2*HD, bnm + 2*HD, a);
    run_gcn(src2, dst2, ew2, a, Wd + 2*HD*HD, bd + 2*HD, 1.f, h2, L2N, wb, pDeg);
    k_lrelu<<<cdiv(L2N * HD, 256), 256>>>(h2, L2N * HD);

    // ---- down: pool3 + GCN3 -> o (bottom, no lrelu) ----
    run_pool(h2, L2N, L3N, Wp + 2*HD, perm3, src2, dst2, ew2,
             src3, dst3, ew3, gn + 3*HD, bnm + 3*HD, a);
    run_gcn(src3, dst3, ew3, a, Wd + 3*HD*HD, bd + 3*HD, 1.f, o, L3N, wb, pDeg);

    // ---- up 0: n=12500 ----
    cudaMemcpyAsync(a, h2, (size_t)L2N * HD * sizeof(float), cudaMemcpyDeviceToDevice);
    k_unpool<<<L3N, HD>>>(a, perm3, o);
    run_gcn(src2, dst2, ew2, a, Wu, bu, 2.f, o, L2N, wb, pDeg);
    k_lrelu<<<cdiv(L2N * HD, 256), 256>>>(o, L2N * HD);

    // ---- up 1: n=25000 ----
    cudaMemcpyAsync(a, h1, (size_t)L1N * HD * sizeof(float), cudaMemcpyDeviceToDevice);
    k_unpool<<<L2N, HD>>>(a, perm2, o);
    run_gcn(src1, dst1, ew1, a, Wu + HD*HD, bu + HD, 2.f, o, L1N, wb, pDeg);
    k_lrelu<<<cdiv(L1N * HD, 256), 256>>>(o, L1N * HD);

    // ---- up 2: n=50000 (no lrelu) ----
    cudaMemcpyAsync(a, h0, (size_t)NN * HD * sizeof(float), cudaMemcpyDeviceToDevice);
    k_unpool<<<L1N, HD>>>(a, perm1, o);
    run_gcn(src0, dst0, ew0, a, Wu + 2*HD*HD, bu + 2*HD, 2.f, o, NN, wb, pDeg);

    // ---- readout ----
    cudaMemsetAsync(pGs, 0, HD * sizeof(float));
    k_colsum<<<cdiv(NN, 256), 128>>>(o, NN);
    k_final<<<1, 128>>>(Wr, br, gr, brn, out, out_size);
}

// round 3
// speedup vs baseline: 1.5441x; 1.5441x over previous
#include <cuda_runtime.h>
#include <stdint.h>

#define NN 50000
#define L1N 25000
#define L2N 12500
#define L3N 6250
#define EE 800000
#define HD 128
#define BNS 0.9999950000374997f

static inline int cdiv(int a, int b){ return (a + b - 1) / b; }

// ------------------------- device scratch (static, no allocs) -------------------------
__device__ float g_h0[(size_t)NN*HD];
__device__ float g_h1[(size_t)L1N*HD];
__device__ float g_h2[(size_t)L2N*HD];
__device__ float g_a [(size_t)NN*HD];
__device__ float g_w [(size_t)NN*HD];
__device__ float g_o [(size_t)NN*HD];
__device__ float g_ew0[EE];
__device__ int   g_srcl[3][EE];
__device__ int   g_dstl[3][EE];
__device__ float g_ewl[3][EE];
__device__ float g_deg0[NN];
__device__ float g_deg1[L1N];
__device__ float g_deg2[L2N];
__device__ float g_deg3[L3N];
__device__ float g_dinv[NN];
__device__ float g_selfc[NN];
__device__ float g_s[NN];
__device__ unsigned g_u[NN];
__device__ int g_perm1[L1N];
__device__ int g_perm2[L2N];
__device__ int g_perm3[L3N];
__device__ int g_pos1[NN];
__device__ int g_pos2[L1N];
__device__ int g_pos3[L2N];
__device__ unsigned g_hist[2048];
__device__ unsigned g_mn, g_mx;
__device__ unsigned g_prefix;
__device__ int g_krem;
__device__ unsigned g_thr;
__device__ int g_T;
__device__ unsigned g_done;
__device__ int g_pcnt, g_eqcnt;
__device__ int g_ecnt[3];
__device__ float g_gsum[HD];

// ------------------------- helpers -------------------------
__device__ __forceinline__ unsigned fenc(float f){
    unsigned u = __float_as_uint(f);
    return (u & 0x80000000u) ? ~u : (u | 0x80000000u);
}
__device__ __forceinline__ float fdec(unsigned u){
    return __uint_as_float((u & 0x80000000u) ? (u ^ 0x80000000u) : ~u);
}
__device__ __forceinline__ unsigned ldcgu(const unsigned* p){
    unsigned v; asm volatile("ld.global.cg.u32 %0, [%1];" : "=r"(v) : "l"(p)); return v;
}
__device__ __forceinline__ unsigned long long dup2(float x){
    unsigned long long r; unsigned u = __float_as_uint(x);
    asm("mov.b64 %0, {%1, %1};" : "=l"(r) : "r"(u));
    return r;
}
#define FMA2(d, a, b) asm("fma.rn.f32x2 %0, %1, %2, %0;" : "+l"(d) : "l"(a), "l"(b))
__device__ __forceinline__ float lrelu1(float v){ return v > 0.f ? v : 0.01f * v; }
__device__ __forceinline__ float4 lrelu4(float4 v){
    v.x = lrelu1(v.x); v.y = lrelu1(v.y); v.z = lrelu1(v.z); v.w = lrelu1(v.w);
    return v;
}

// ------------------------- init -------------------------
__global__ void k_init(){
    int i = blockIdx.x * blockDim.x + threadIdx.x;
    if (i < 2048) g_hist[i] = 0u;
    if (i == 0){ g_mn = 0xFFFFFFFFu; g_mx = 0u; g_done = 0u; }
    if (i < NN) g_deg0[i] = 0.f;
}

// ------------------------- edge embedding + min/max -------------------------
__global__ void k_ew(const float* __restrict__ ea, const float* __restrict__ ww,
                     const float* __restrict__ wb){
    int e = blockIdx.x * blockDim.x + threadIdx.x;
    bool inb = e < EE;
    float acc = 0.f;
    if (inb){
        acc = wb[0];
        const float4* a4 = (const float4*)(ea + (size_t)e * 16);
        const float4* w4 = (const float4*)ww;
        #pragma unroll
        for (int j = 0; j < 4; j++){
            float4 a = a4[j], w = w4[j];
            acc += a.x*w.x + a.y*w.y + a.z*w.z + a.w*w.w;
        }
        g_ew0[e] = acc;
    }
    unsigned em = inb ? fenc(acc) : 0xFFFFFFFFu;
    unsigned eM = inb ? fenc(acc) : 0u;
    __shared__ unsigned smn[256], smx[256];
    smn[threadIdx.x] = em; smx[threadIdx.x] = eM;
    __syncthreads();
    for (int s = 128; s > 0; s >>= 1){
        if (threadIdx.x < s){
            smn[threadIdx.x] = min(smn[threadIdx.x], smn[threadIdx.x + s]);
            smx[threadIdx.x] = max(smx[threadIdx.x], smx[threadIdx.x + s]);
        }
        __syncthreads();
    }
    if (threadIdx.x == 0){ atomicMin(&g_mn, smn[0]); atomicMax(&g_mx, smx[0]); }
}

// normalize edge weights + accumulate level-0 degree
__global__ void k_ewfin(const int* __restrict__ dst0){
    int e = blockIdx.x * blockDim.x + threadIdx.x;
    if (e >= EE) return;
    float mn = fdec(g_mn), mx = fdec(g_mx);
    float w = (g_ew0[e] - mn) / ((mx - mn) + 1e-7f);
    g_ew0[e] = w;
    atomicAdd(&g_deg0[dst0[e]], w);
}

// ------------------------- GCN pieces -------------------------
__global__ void k_dinv(const float* __restrict__ deg, int n, float fill){
    int i = blockIdx.x * blockDim.x + threadIdx.x;
    if (i >= n) return;
    float dg = deg[i] + fill;
    g_dinv[i]  = rsqrtf(dg);
    g_selfc[i] = fill / dg;
}

// C[n,128] = A'[n,128] @ W[128,128]; out = selfc*C + bias (A' = optional BN(A))
// f32x2 packed-FMA, 128x128 tile, 8x8 microtile, 256 threads.
__global__ void __launch_bounds__(256, 2) k_mm(
        const float* __restrict__ A, const float* __restrict__ W,
        float* __restrict__ C, float* __restrict__ out,
        const float* __restrict__ bias,
        const float* __restrict__ bns, const float* __restrict__ bnb, int n){
    __shared__ __align__(16) float As[16][132];
    __shared__ __align__(16) float Bs[16][128];
    int tid = threadIdx.x;
    int tx = tid & 15, ty = tid >> 4;
    int bm0 = blockIdx.x * 128;
    unsigned long long acc[4][8];
    #pragma unroll
    for (int p = 0; p < 4; p++)
        #pragma unroll
        for (int c = 0; c < 8; c++) acc[p][c] = 0ull;

    for (int k0 = 0; k0 < 128; k0 += 16){
        #pragma unroll
        for (int i = 0; i < 2; i++){
            int idx = tid + i * 256;
            int r = idx >> 2, c4 = idx & 3;
            int grow = bm0 + r;
            float4 v = make_float4(0.f, 0.f, 0.f, 0.f);
            if (grow < n) v = *(const float4*)(A + (size_t)grow * 128 + k0 + c4 * 4);
            if (bns){
                float4 s4 = *(const float4*)(bns + k0 + c4 * 4);
                float4 o4 = *(const float4*)(bnb + k0 + c4 * 4);
                v.x = v.x * (s4.x * BNS) + o4.x;
                v.y = v.y * (s4.y * BNS) + o4.y;
                v.z = v.z * (s4.z * BNS) + o4.z;
                v.w = v.w * (s4.w * BNS) + o4.w;
            }
            As[c4*4+0][r] = v.x; As[c4*4+1][r] = v.y;
            As[c4*4+2][r] = v.z; As[c4*4+3][r] = v.w;
        }
        #pragma unroll
        for (int i = 0; i < 2; i++){
            int idx = tid + i * 256;
            int kk = idx >> 5, c = idx & 31;
            *(float4*)&Bs[kk][c*4] = *(const float4*)(W + (size_t)(k0 + kk) * 128 + c * 4);
        }
        __syncthreads();
        #pragma unroll
        for (int kk = 0; kk < 16; kk++){
            ulonglong2 aA = *(const ulonglong2*)&As[kk][ty*8];
            ulonglong2 aB = *(const ulonglong2*)&As[kk][ty*8+4];
            float4 b0 = *(const float4*)&Bs[kk][tx*8];
            float4 b1 = *(const float4*)&Bs[kk][tx*8+4];
            unsigned long long ap[4] = { aA.x, aA.y, aB.x, aB.y };
            unsigned long long bb[8] = { dup2(b0.x), dup2(b0.y), dup2(b0.z), dup2(b0.w),
                                         dup2(b1.x), dup2(b1.y), dup2(b1.z), dup2(b1.w) };
            #pragma unroll
            for (int p = 0; p < 4; p++)
                #pragma unroll
                for (int c = 0; c < 8; c++)
                    FMA2(acc[p][c], ap[p], bb[c]);
        }
        __syncthreads();
    }
    float4 b4a = *(const float4*)(bias + tx*8);
    float4 b4b = *(const float4*)(bias + tx*8 + 4);
    #pragma unroll
    for (int p = 0; p < 4; p++){
        #pragma unroll
        for (int j = 0; j < 2; j++){
            int row = bm0 + ty*8 + 2*p + j;
            if (row >= n) continue;
            float vals[8];
            #pragma unroll
            for (int c = 0; c < 8; c++){
                unsigned long long u = acc[p][c];
                vals[c] = j ? __uint_as_float((unsigned)(u >> 32))
                            : __uint_as_float((unsigned)u);
            }
            float sc = g_selfc[row];
            float4 lo = make_float4(vals[0], vals[1], vals[2], vals[3]);
            float4 hi = make_float4(vals[4], vals[5], vals[6], vals[7]);
            *(float4*)(C + (size_t)row * 128 + tx*8)     = lo;
            *(float4*)(C + (size_t)row * 128 + tx*8 + 4) = hi;
            float4 o1 = make_float4(sc*vals[0] + b4a.x, sc*vals[1] + b4a.y,
                                    sc*vals[2] + b4a.z, sc*vals[3] + b4a.w);
            float4 o2 = make_float4(sc*vals[4] + b4b.x, sc*vals[5] + b4b.y,
                                    sc*vals[6] + b4b.z, sc*vals[7] + b4b.w);
            *(float4*)(out + (size_t)row * 128 + tx*8)     = o1;
            *(float4*)(out + (size_t)row * 128 + tx*8 + 4) = o2;
        }
    }
}

// grid-stride warp-per-edge scatter with vector reduction
__global__ void k_scatter(const int* __restrict__ src, const int* __restrict__ dst,
                          const float* __restrict__ w, const float* __restrict__ hp,
                          float* __restrict__ out, int fixedcnt, const int* __restrict__ dyncnt){
    int cnt = dyncnt ? *dyncnt : fixedcnt;
    int lane = threadIdx.x & 31;
    int wid = (blockIdx.x * blockDim.x + threadIdx.x) >> 5;
    int nwarp = (gridDim.x * blockDim.x) >> 5;
    for (int e = wid; e < cnt; e += nwarp){
        float we = __ldg(&w[e]);
        if (we == 0.f) continue;
        int s = src[e], d = dst[e];
        float c = g_dinv[s] * we * g_dinv[d];
        float4 v = *(const float4*)(hp + (size_t)s * 128 + lane * 4);
        float* addr = out + (size_t)d * 128 + lane * 4;
        asm volatile("red.global.add.v4.f32 [%0], {%1, %2, %3, %4};"
                     :: "l"(addr), "f"(v.x*c), "f"(v.y*c), "f"(v.z*c), "f"(v.w*c) : "memory");
    }
}

// ------------------------- TopK pooling -------------------------
// warp per node; lrelu applied on the fly; inline ||p||
__global__ void k_score(const float* __restrict__ h, const float* __restrict__ p, int n){
    int wid = (blockIdx.x * blockDim.x + threadIdx.x) >> 5;
    int lane = threadIdx.x & 31;
    if (wid >= n) return;
    float4 pv = *(const float4*)(p + lane * 4);
    float4 hv = lrelu4(*(const float4*)(h + (size_t)wid * 128 + lane * 4));
    float d = hv.x*pv.x + hv.y*pv.y + hv.z*pv.z + hv.w*pv.w;
    float pp = pv.x*pv.x + pv.y*pv.y + pv.z*pv.z + pv.w*pv.w;
    #pragma unroll
    for (int o = 16; o > 0; o >>= 1){
        d  += __shfl_xor_sync(0xffffffffu, d, o);
        pp += __shfl_xor_sync(0xffffffffu, pp, o);
    }
    if (lane == 0){
        float v = tanhf(d / sqrtf(pp));
        g_s[wid] = v;
        g_u[wid] = fenc(v);
    }
}

// fused histogram + (last block) radix-select pass
__global__ void k_histsel(int n, int pass, int k0){
    __shared__ unsigned sh[2048];
    __shared__ int amLast;
    for (int j = threadIdx.x; j < 2048; j += blockDim.x) sh[j] = 0u;
    __syncthreads();
    unsigned pref = g_prefix;
    for (int i = blockIdx.x * blockDim.x + threadIdx.x; i < n; i += gridDim.x * blockDim.x){
        unsigned ui = g_u[i];
        if (pass == 0) atomicAdd(&sh[ui >> 21], 1u);
        else if (pass == 1){ if ((ui >> 21) == pref) atomicAdd(&sh[(ui >> 10) & 2047u], 1u); }
        else            { if ((ui >> 10) == pref) atomicAdd(&sh[ui & 1023u], 1u); }
    }
    __syncthreads();
    for (int j = threadIdx.x; j < 2048; j += blockDim.x){
        unsigned c = sh[j];
        if (c) atomicAdd(&g_hist[j], c);
    }
    __threadfence();
    __syncthreads();
    if (threadIdx.x == 0)
        amLast = (atomicAdd(&g_done, 1u) == (unsigned)(gridDim.x - 1));
    __syncthreads();
    if (!amLast || threadIdx.x >= 32) return;
    int lane = threadIdx.x;
    int nbins = (pass < 2) ? 2048 : 1024;
    int chunk = nbins >> 5;
    int k = (pass == 0) ? k0 : g_krem;
    int base = nbins - 1 - lane * chunk;
    unsigned cnt = 0;
    for (int j = 0; j < chunk; j++) cnt += ldcgu(&g_hist[base - j]);
    unsigned pre = cnt;
    #pragma unroll
    for (int off = 1; off < 32; off <<= 1){
        unsigned t = __shfl_up_sync(0xffffffffu, pre, off);
        if (lane >= off) pre += t;
    }
    pre -= cnt;
    bool sel = (pre < (unsigned)k) && ((unsigned)k <= pre + cnt);
    unsigned m = __ballot_sync(0xffffffffu, sel);
    int L = __ffs(m) - 1;
    if (lane == L){
        unsigned run = pre;
        for (int j = 0; j < chunk; j++){
            int b = base - j;
            unsigned c = ldcgu(&g_hist[b]);
            if (run + c >= (unsigned)k){
                if (pass == 0)      g_prefix = (unsigned)b;
                else if (pass == 1) g_prefix = (g_prefix << 11) | (unsigned)b;
                else { g_thr = (g_prefix << 10) | (unsigned)b; g_T = k - (int)run;
                       g_pcnt = 0; g_eqcnt = 0; }
                g_krem = k - (int)run;
                break;
            }
            run += c;
        }
    }
    __syncwarp();
    for (int j = lane; j < 2048; j += 32) g_hist[j] = 0u;
    if (lane == 0) atomicExch(&g_done, 0u);
}

// atomic partition -> perm/pos; also zero new edge count + new degree
__global__ void k_partition(int n, int k, int* __restrict__ perm, int* __restrict__ pos,
                            float* __restrict__ degn, int lvl){
    int i = blockIdx.x * blockDim.x + threadIdx.x;
    if (i == 0) g_ecnt[lvl] = 0;
    if (i < k) degn[i] = 0.f;
    if (i >= n) return;
    unsigned ui = g_u[i], ut = g_thr;
    int p = -1;
    if (ui > ut) p = atomicAdd(&g_pcnt, 1);
    else if (ui == ut){
        int t = atomicAdd(&g_eqcnt, 1);
        if (t < g_T) p = atomicAdd(&g_pcnt, 1);
    }
    pos[i] = p;
    if (p >= 0) perm[p] = i;
}

// compact valid edges + accumulate new degree
__global__ void k_relabel(const int* __restrict__ s, const int* __restrict__ d,
                          const float* __restrict__ w, const int* __restrict__ pos,
                          int* __restrict__ ns, int* __restrict__ nd, float* __restrict__ nw,
                          float* __restrict__ degn, int lvl,
                          int fixedcnt, const int* __restrict__ dyncnt){
    int cnt = dyncnt ? *dyncnt : fixedcnt;
    for (int e = blockIdx.x * blockDim.x + threadIdx.x; e < cnt; e += gridDim.x * blockDim.x){
        int a = pos[s[e]], b = pos[d[e]];
        if (a >= 0 && b >= 0){
            int j = atomicAdd(&g_ecnt[lvl], 1);
            float we = w[e];
            ns[j] = a; nd[j] = b; nw[j] = we;
            atomicAdd(&degn[b], we);
        }
    }
}

// out[new] = lrelu(h[old]) * score[old] * (gn*BNS) + bn
__global__ void k_pool(const float* __restrict__ h, const int* __restrict__ perm,
                       const float* __restrict__ gn, const float* __restrict__ bn,
                       float* __restrict__ out, int k){
    int i = blockIdx.x * blockDim.x + threadIdx.x;
    if (i >= k * 32) return;
    int r = i >> 5, d4 = i & 31;
    int old = perm[r];
    float sc = g_s[old];
    float4 v = lrelu4(*(const float4*)(h + (size_t)old * 128 + d4 * 4));
    float4 g4 = *(const float4*)(gn + d4 * 4);
    float4 b4 = *(const float4*)(bn + d4 * 4);
    v.x = v.x * sc * (g4.x * BNS) + b4.x;
    v.y = v.y * sc * (g4.y * BNS) + b4.y;
    v.z = v.z * sc * (g4.z * BNS) + b4.z;
    v.w = v.w * sc * (g4.w * BNS) + b4.w;
    *(float4*)(out + (size_t)r * 128 + d4 * 4) = v;
}

// a = lrelu(res) + unpool(u)   (u optionally lrelu'd)
__global__ void k_resup(const float* __restrict__ res, const int* __restrict__ pos,
                        const float* __restrict__ u, float* __restrict__ a,
                        int n, int uflag){
    int i = blockIdx.x * blockDim.x + threadIdx.x;
    if (i >= n * 32) return;
    int r = i >> 5, d4 = i & 31;
    float4 v = lrelu4(*(const float4*)(res + (size_t)r * 128 + d4 * 4));
    int pr = pos[r];
    if (pr >= 0){
        float4 uv = *(const float4*)(u + (size_t)pr * 128 + d4 * 4);
        if (uflag) uv = lrelu4(uv);
        v.x += uv.x; v.y += uv.y; v.z += uv.z; v.w += uv.w;
    }
    *(float4*)(a + (size_t)r * 128 + d4 * 4) = v;
}

// ------------------------- readout -------------------------
__global__ void k_colsum(const float* __restrict__ h, int n){
    int d = threadIdx.x;
    int r0 = blockIdx.x * 256;
    int rend = min(r0 + 256, n);
    float acc = 0.f;
    for (int r = r0; r < rend; r++) acc += h[(size_t)r * 128 + d];
    atomicAdd(&g_gsum[d], acc);
}

__global__ void k_final(const float* __restrict__ Wr, const float* __restrict__ br,
                        const float* __restrict__ gr, const float* __restrict__ brn,
                        float* __restrict__ out, int osz){
    __shared__ float gs[HD];
    int t = threadIdx.x;
    gs[t] = g_gsum[t];
    __syncthreads();
    float acc = br[t];
    for (int d2 = 0; d2 < HD; d2++) acc += gs[d2] * Wr[d2 * HD + t];
    float r = acc * (gr[t] * BNS) + brn[t];
    if (t < osz) out[t] = r;
}

// ------------------------- host orchestration -------------------------
extern "C" void kernel_launch(void* const* d_in, const int* in_sizes, int n_in,
                              void* d_out, int out_size){
    const float* x   = (const float*)d_in[0];
    const int*   ei  = (const int*)d_in[1];
    const float* ea  = (const float*)d_in[2];
    const float* Wew = (const float*)d_in[3];
    const float* Web = (const float*)d_in[4];
    const float* Wd  = (const float*)d_in[5];
    const float* bd  = (const float*)d_in[6];
    const float* Wp  = (const float*)d_in[7];
    const float* Wu  = (const float*)d_in[8];
    const float* bu  = (const float*)d_in[9];
    const float* gn  = (const float*)d_in[10];
    const float* bnm = (const float*)d_in[11];
    const float* Wr  = (const float*)d_in[12];
    const float* br  = (const float*)d_in[13];
    const float* gr  = (const float*)d_in[14];
    const float* brn = (const float*)d_in[15];
    float* out = (float*)d_out;

    void *pH0,*pH1,*pH2,*pA,*pW,*pO,*pEw0,*pSrc,*pDst,*pEwl;
    void *pP1,*pP2,*pP3,*pQ1,*pQ2,*pQ3,*pD0,*pD1,*pD2,*pD3,*pGs,*pEc;
    cudaGetSymbolAddress(&pH0, g_h0);  cudaGetSymbolAddress(&pH1, g_h1);
    cudaGetSymbolAddress(&pH2, g_h2);  cudaGetSymbolAddress(&pA, g_a);
    cudaGetSymbolAddress(&pW, g_w);    cudaGetSymbolAddress(&pO, g_o);
    cudaGetSymbolAddress(&pEw0, g_ew0);
    cudaGetSymbolAddress(&pSrc, g_srcl); cudaGetSymbolAddress(&pDst, g_dstl);
    cudaGetSymbolAddress(&pEwl, g_ewl);
    cudaGetSymbolAddress(&pP1, g_perm1); cudaGetSymbolAddress(&pP2, g_perm2);
    cudaGetSymbolAddress(&pP3, g_perm3);
    cudaGetSymbolAddress(&pQ1, g_pos1);  cudaGetSymbolAddress(&pQ2, g_pos2);
    cudaGetSymbolAddress(&pQ3, g_pos3);
    cudaGetSymbolAddress(&pD0, g_deg0);  cudaGetSymbolAddress(&pD1, g_deg1);
    cudaGetSymbolAddress(&pD2, g_deg2);  cudaGetSymbolAddress(&pD3, g_deg3);
    cudaGetSymbolAddress(&pGs, g_gsum);  cudaGetSymbolAddress(&pEc, g_ecnt);

    float* h0=(float*)pH0; float* h1=(float*)pH1; float* h2=(float*)pH2;
    float* a =(float*)pA;  float* wb=(float*)pW;  float* o =(float*)pO;
    float* ew0=(float*)pEw0;
    int* srcB=(int*)pSrc; int* dstB=(int*)pDst; float* ewB=(float*)pEwl;
    int* src1=srcB;        int* dst1=dstB;        float* ew1=ewB;
    int* src2=srcB+EE;     int* dst2=dstB+EE;     float* ew2=ewB+EE;
    int* src3=srcB+2*EE;   int* dst3=dstB+2*EE;   float* ew3=ewB+2*EE;
    int* perm1=(int*)pP1;  int* perm2=(int*)pP2;  int* perm3=(int*)pP3;
    int* pos1=(int*)pQ1;   int* pos2=(int*)pQ2;   int* pos3=(int*)pQ3;
    float* deg0=(float*)pD0; float* deg1=(float*)pD1;
    float* deg2=(float*)pD2; float* deg3=(float*)pD3;
    int* ecnt=(int*)pEc;
    const int* src0 = ei;
    const int* dst0 = ei + EE;

    // ---- setup: edge embedding + norm + level-0 degree ----
    k_init<<<cdiv(NN,256),256>>>();
    k_ew<<<cdiv(EE,256),256>>>(ea, Wew, Web);
    k_ewfin<<<cdiv(EE,256),256>>>(dst0);

    // ---- GCN0 (BN fused into A-load) -> h0 (raw, lrelu applied by consumers) ----
    k_dinv<<<cdiv(NN,256),256>>>(deg0, NN, 1.f);
    k_mm<<<cdiv(NN,128),256>>>(x, Wd, wb, h0, bd, gn, bnm, NN);
    k_scatter<<<4096,256>>>(src0, dst0, ew0, wb, h0, EE, nullptr);

    // ---- pool1 + GCN1 -> h1 ----
    k_score<<<cdiv(NN,8),256>>>(h0, Wp, NN);
    for (int p = 0; p < 3; p++) k_histsel<<<120,256>>>(NN, p, L1N);
    k_partition<<<cdiv(NN,256),256>>>(NN, L1N, perm1, pos1, deg1, 0);
    k_relabel<<<2048,256>>>(src0, dst0, ew0, pos1, src1, dst1, ew1, deg1, 0, EE, nullptr);
    k_pool<<<cdiv(L1N*32,256),256>>>(h0, perm1, gn+HD, bnm+HD, a, L1N);
    k_dinv<<<cdiv(L1N,256),256>>>(deg1, L1N, 1.f);
    k_mm<<<cdiv(L1N,128),256>>>(a, Wd+HD*HD, wb, h1, bd+HD, nullptr, nullptr, L1N);
    k_scatter<<<2048,256>>>(src1, dst1, ew1, wb, h1, 0, ecnt+0);

    // ---- pool2 + GCN2 -> h2 ----
    k_score<<<cdiv(L1N,8),256>>>(h1, Wp+HD, L1N);
    for (int p = 0; p < 3; p++) k_histsel<<<120,256>>>(L1N, p, L2N);
    k_partition<<<cdiv(L1N,256),256>>>(L1N, L2N, perm2, pos2, deg2, 1);
    k_relabel<<<2048,256>>>(src1, dst1, ew1, pos2, src2, dst2, ew2, deg2, 1, 0, ecnt+0);
    k_pool<<<cdiv(L2N*32,256),256>>>(h1, perm2, gn+2*HD, bnm+2*HD, a, L2N);
    k_dinv<<<cdiv(L2N,256),256>>>(deg2, L2N, 1.f);
    k_mm<<<cdiv(L2N,128),256>>>(a, Wd+2*HD*HD, wb, h2, bd+2*HD, nullptr, nullptr, L2N);
    k_scatter<<<2048,256>>>(src2, dst2, ew2, wb, h2, 0, ecnt+1);

    // ---- pool3 + GCN3 -> o (bottom, no lrelu) ----
    k_score<<<cdiv(L2N,8),256>>>(h2, Wp+2*HD, L2N);
    for (int p = 0; p < 3; p++) k_histsel<<<120,256>>>(L2N, p, L3N);
    k_partition<<<cdiv(L2N,256),256>>>(L2N, L3N, perm3, pos3, deg3, 2);
    k_relabel<<<2048,256>>>(src2, dst2, ew2, pos3, src3, dst3, ew3, deg3, 2, 0, ecnt+1);
    k_pool<<<cdiv(L3N*32,256),256>>>(h2, perm3, gn+3*HD, bnm+3*HD, a, L3N);
    k_dinv<<<cdiv(L3N,256),256>>>(deg3, L3N, 1.f);
    k_mm<<<cdiv(L3N,128),256>>>(a, Wd+3*HD*HD, wb, o, bd+3*HD, nullptr, nullptr, L3N);
    k_scatter<<<2048,256>>>(src3, dst3, ew3, wb, o, 0, ecnt+2);

    // ---- up 0 (n=12500): res=h2, unpool bottom o (no lrelu on u) ----
    k_resup<<<cdiv(L2N*32,256),256>>>(h2, pos3, o, a, L2N, 0);
    k_dinv<<<cdiv(L2N,256),256>>>(deg2, L2N, 2.f);
    k_mm<<<cdiv(L2N,128),256>>>(a, Wu, wb, o, bu, nullptr, nullptr, L2N);
    k_scatter<<<2048,256>>>(src2, dst2, ew2, wb, o, 0, ecnt+1);

    // ---- up 1 (n=25000) ----
    k_resup<<<cdiv(L1N*32,256),256>>>(h1, pos2, o, a, L1N, 1);
    k_dinv<<<cdiv(L1N,256),256>>>(deg1, L1N, 2.f);
    k_mm<<<cdiv(L1N,128),256>>>(a, Wu+HD*HD, wb, o, bu+HD, nullptr, nullptr, L1N);
    k_scatter<<<2048,256>>>(src1, dst1, ew1, wb, o, 0, ecnt+0);

    // ---- up 2 (n=50000, no lrelu after) ----
    k_resup<<<cdiv(NN*32,256),256>>>(h0, pos1, o, a, NN, 1);
    k_dinv<<<cdiv(NN,256),256>>>(deg0, NN, 2.f);
    k_mm<<<cdiv(NN,128),256>>>(a, Wu+2*HD*HD, wb, o, bu+2*HD, nullptr, nullptr, NN);
    k_scatter<<<4096,256>>>(src0, dst0, ew0, wb, o, EE, nullptr);

    // ---- readout ----
    cudaMemsetAsync(pGs, 0, HD * sizeof(float));
    k_colsum<<<cdiv(NN,256),128>>>(o, NN);
    k_final<<<1,128>>>(Wr, br, gr, brn, out, out_size);
}

// round 4
// speedup vs baseline: 1.7620x; 1.1412x over previous
#include <cuda_runtime.h>
#include <stdint.h>

#define NN 50000
#define L1N 25000
#define L2N 12500
#define L3N 6250
#define EE 800000
#define HD 128
#define BNS 0.9999950000374997f

static inline int cdiv(int a, int b){ return (a + b - 1) / b; }

// ------------------------- device scratch (static, no allocs) -------------------------
__device__ float g_h0[(size_t)NN*HD];
__device__ float g_h1[(size_t)L1N*HD];
__device__ float g_h2[(size_t)L2N*HD];
__device__ float g_w [(size_t)NN*HD];   // C = A@W
__device__ float g_o [(size_t)NN*HD];
__device__ float g_bb[(size_t)NN*HD];
__device__ float g_ew0[EE];
__device__ int   g_srcl[3][EE];
__device__ int   g_dstl[3][EE];
__device__ float g_ewl[3][EE];
// CSR per level
__device__ int   g_csrc[4][EE];
__device__ float g_cc1[4][EE];
__device__ float g_cc2[4][EE];
__device__ int   g_rp0[NN+1];
__device__ int   g_rp1[L1N+1];
__device__ int   g_rp2[L2N+1];
__device__ int   g_rp3[L3N+1];
__device__ int   g_cur[NN];
__device__ int   g_cnt[NN];
__device__ float g_dv1[NN];
__device__ float g_dv2[NN];
__device__ float g_deg0[NN];
__device__ float g_deg1[L1N];
__device__ float g_deg2[L2N];
__device__ float g_deg3[L3N];
__device__ float g_s[NN];
__device__ unsigned g_u[NN];
__device__ int g_perm1[L1N];
__device__ int g_perm2[L2N];
__device__ int g_perm3[L3N];
__device__ int g_pos1[NN];
__device__ int g_pos2[L1N];
__device__ int g_pos3[L2N];
__device__ unsigned g_hist[2048];
__device__ unsigned g_mn, g_mx;
__device__ unsigned g_done;
__device__ unsigned g_thr;
__device__ int g_T;
__device__ int g_pcnt, g_eqcnt;
__device__ int g_ecnt[3];
__device__ float g_gsum[HD];

// ------------------------- helpers -------------------------
__device__ __forceinline__ unsigned fenc(float f){
    unsigned u = __float_as_uint(f);
    return (u & 0x80000000u) ? ~u : (u | 0x80000000u);
}
__device__ __forceinline__ float fdec(unsigned u){
    return __uint_as_float((u & 0x80000000u) ? (u ^ 0x80000000u) : ~u);
}
__device__ __forceinline__ unsigned long long dup2(float x){
    unsigned long long r; unsigned u = __float_as_uint(x);
    asm("mov.b64 %0, {%1, %1};" : "=l"(r) : "r"(u));
    return r;
}
#define FMA2(d, a, b) asm("fma.rn.f32x2 %0, %1, %2, %0;" : "+l"(d) : "l"(a), "l"(b))
__device__ __forceinline__ float lrelu1(float v){ return v > 0.f ? v : 0.01f * v; }
__device__ __forceinline__ float4 lrelu4(float4 v){
    v.x = lrelu1(v.x); v.y = lrelu1(v.y); v.z = lrelu1(v.z); v.w = lrelu1(v.w);
    return v;
}

// ------------------------- init -------------------------
__global__ void k_init(){
    int i = blockIdx.x * blockDim.x + threadIdx.x;
    if (i < 2048) g_hist[i] = 0u;
    if (i == 0){ g_mn = 0xFFFFFFFFu; g_mx = 0u; g_done = 0u; }
    if (i < NN){ g_deg0[i] = 0.f; g_cnt[i] = 0; }
}

// ------------------------- edge embedding + min/max -------------------------
__global__ void k_ew(const float* __restrict__ ea, const float* __restrict__ ww,
                     const float* __restrict__ wb){
    int e = blockIdx.x * blockDim.x + threadIdx.x;
    bool inb = e < EE;
    float acc = 0.f;
    if (inb){
        acc = wb[0];
        const float4* a4 = (const float4*)(ea + (size_t)e * 16);
        const float4* w4 = (const float4*)ww;
        #pragma unroll
        for (int j = 0; j < 4; j++){
            float4 a = a4[j], w = w4[j];
            acc += a.x*w.x + a.y*w.y + a.z*w.z + a.w*w.w;
        }
        g_ew0[e] = acc;
    }
    unsigned em = inb ? fenc(acc) : 0xFFFFFFFFu;
    unsigned eM = inb ? fenc(acc) : 0u;
    __shared__ unsigned smn[256], smx[256];
    smn[threadIdx.x] = em; smx[threadIdx.x] = eM;
    __syncthreads();
    for (int s = 128; s > 0; s >>= 1){
        if (threadIdx.x < s){
            smn[threadIdx.x] = min(smn[threadIdx.x], smn[threadIdx.x + s]);
            smx[threadIdx.x] = max(smx[threadIdx.x], smx[threadIdx.x + s]);
        }
        __syncthreads();
    }
    if (threadIdx.x == 0){ atomicMin(&g_mn, smn[0]); atomicMax(&g_mx, smx[0]); }
}

// normalize edge weights + accumulate level-0 degree + int counts
__global__ void k_ewfin(const int* __restrict__ dst0){
    int e = blockIdx.x * blockDim.x + threadIdx.x;
    if (e >= EE) return;
    float mn = fdec(g_mn), mx = fdec(g_mx);
    float w = (g_ew0[e] - mn) / ((mx - mn) + 1e-7f);
    g_ew0[e] = w;
    int d = dst0[e];
    atomicAdd(&g_deg0[d], w);
    atomicAdd(&g_cnt[d], 1);
}

// ------------------------- scan: rowptr + cursors + dinv1/dinv2 -------------------------
__global__ void __launch_bounds__(1024) k_scan(const float* __restrict__ deg, int n,
                                               int* __restrict__ rp){
    __shared__ int wsum[32];
    __shared__ int sCarry;
    int tid = threadIdx.x;
    int lane = tid & 31, w = tid >> 5;
    if (tid == 0) sCarry = 0;
    __syncthreads();
    for (int c0 = 0; c0 < n; c0 += 1024){
        int i = c0 + tid;
        int v = (i < n) ? g_cnt[i] : 0;
        int x = v;
        #pragma unroll
        for (int off = 1; off < 32; off <<= 1){
            int t = __shfl_up_sync(0xffffffffu, x, off);
            if (lane >= off) x += t;
        }
        if (lane == 31) wsum[w] = x;
        __syncthreads();
        if (w == 0){
            int y = wsum[lane];
            #pragma unroll
            for (int off = 1; off < 32; off <<= 1){
                int t = __shfl_up_sync(0xffffffffu, y, off);
                if (lane >= off) y += t;
            }
            wsum[lane] = y;
        }
        __syncthreads();
        int warpoff = (w > 0) ? wsum[w-1] : 0;
        int incl = x + warpoff + sCarry;
        int excl = incl - v;
        if (i < n){
            rp[i] = excl; g_cur[i] = excl;
            float dg = deg[i];
            g_dv1[i] = rsqrtf(dg + 1.f);
            g_dv2[i] = rsqrtf(dg + 2.f);
        }
        __syncthreads();
        if (tid == 1023) sCarry = incl;
        __syncthreads();
    }
    if (tid == 0) rp[n] = sCarry;
}

// ------------------------- CSR fill (precompute down & up coefficients) ----------------
__global__ void k_fill(const int* __restrict__ s, const int* __restrict__ d,
                       const float* __restrict__ w, int fixedcnt,
                       const int* __restrict__ dyncnt,
                       int* __restrict__ csrc, float* __restrict__ cc1,
                       float* __restrict__ cc2){
    int cnt = dyncnt ? *dyncnt : fixedcnt;
    for (int e = blockIdx.x * blockDim.x + threadIdx.x; e < cnt;
         e += gridDim.x * blockDim.x){
        int a = s[e], b = d[e];
        float we = w[e];
        int slot = atomicAdd(&g_cur[b], 1);
        csrc[slot] = a;
        cc1[slot] = g_dv1[a] * we * g_dv1[b];
        cc2[slot] = g_dv2[a] * we * g_dv2[b];
    }
}

// ------------------------- fused GEMM -------------------------
// A-load modes: bn (bns!=0), pool (perm!=0), resup (pos!=0), plain
// C = Aload(A) @ W ; out = (fill/(deg+fill))*C + bias
__global__ void __launch_bounds__(256, 2) k_mm(
        const float* __restrict__ A, const float* __restrict__ W,
        float* __restrict__ C, float* __restrict__ out,
        const float* __restrict__ bias,
        const float* __restrict__ bns, const float* __restrict__ bnb,
        const int* __restrict__ perm,
        const int* __restrict__ pos, const float* __restrict__ uu, int uflag,
        const float* __restrict__ deg, float fill, int n){
    __shared__ __align__(16) float As[16][132];
    __shared__ __align__(16) float Bs[16][128];
    int tid = threadIdx.x;
    int tx = tid & 15, ty = tid >> 4;
    int bm0 = blockIdx.x * 128;
    unsigned long long acc[4][8];
    #pragma unroll
    for (int p = 0; p < 4; p++)
        #pragma unroll
        for (int c = 0; c < 8; c++) acc[p][c] = 0ull;

    for (int k0 = 0; k0 < 128; k0 += 16){
        #pragma unroll
        for (int i = 0; i < 2; i++){
            int idx = tid + i * 256;
            int r = idx >> 2, c4 = idx & 3;
            int grow = bm0 + r;
            float4 v = make_float4(0.f, 0.f, 0.f, 0.f);
            if (grow < n){
                if (perm){
                    int old = perm[grow];
                    v = lrelu4(*(const float4*)(A + (size_t)old * 128 + k0 + c4 * 4));
                    float sc = g_s[old];
                    float4 s4 = *(const float4*)(bns + k0 + c4 * 4);
                    float4 o4 = *(const float4*)(bnb + k0 + c4 * 4);
                    v.x = v.x * sc * (s4.x * BNS) + o4.x;
                    v.y = v.y * sc * (s4.y * BNS) + o4.y;
                    v.z = v.z * sc * (s4.z * BNS) + o4.z;
                    v.w = v.w * sc * (s4.w * BNS) + o4.w;
                } else if (pos){
                    v = lrelu4(*(const float4*)(A + (size_t)grow * 128 + k0 + c4 * 4));
                    int pr = pos[grow];
                    if (pr >= 0){
                        float4 uv = *(const float4*)(uu + (size_t)pr * 128 + k0 + c4 * 4);
                        if (uflag) uv = lrelu4(uv);
                        v.x += uv.x; v.y += uv.y; v.z += uv.z; v.w += uv.w;
                    }
                } else {
                    v = *(const float4*)(A + (size_t)grow * 128 + k0 + c4 * 4);
                    if (bns){
                        float4 s4 = *(const float4*)(bns + k0 + c4 * 4);
                        float4 o4 = *(const float4*)(bnb + k0 + c4 * 4);
                        v.x = v.x * (s4.x * BNS) + o4.x;
                        v.y = v.y * (s4.y * BNS) + o4.y;
                        v.z = v.z * (s4.z * BNS) + o4.z;
                        v.w = v.w * (s4.w * BNS) + o4.w;
                    }
                }
            }
            As[c4*4+0][r] = v.x; As[c4*4+1][r] = v.y;
            As[c4*4+2][r] = v.z; As[c4*4+3][r] = v.w;
        }
        #pragma unroll
        for (int i = 0; i < 2; i++){
            int idx = tid + i * 256;
            int kk = idx >> 5, c = idx & 31;
            *(float4*)&Bs[kk][c*4] = *(const float4*)(W + (size_t)(k0 + kk) * 128 + c * 4);
        }
        __syncthreads();
        #pragma unroll
        for (int kk = 0; kk < 16; kk++){
            ulonglong2 aA = *(const ulonglong2*)&As[kk][ty*8];
            ulonglong2 aB = *(const ulonglong2*)&As[kk][ty*8+4];
            float4 b0 = *(const float4*)&Bs[kk][tx*8];
            float4 b1 = *(const float4*)&Bs[kk][tx*8+4];
            unsigned long long ap[4] = { aA.x, aA.y, aB.x, aB.y };
            unsigned long long bb[8] = { dup2(b0.x), dup2(b0.y), dup2(b0.z), dup2(b0.w),
                                         dup2(b1.x), dup2(b1.y), dup2(b1.z), dup2(b1.w) };
            #pragma unroll
            for (int p = 0; p < 4; p++)
                #pragma unroll
                for (int c = 0; c < 8; c++)
                    FMA2(acc[p][c], ap[p], bb[c]);
        }
        __syncthreads();
    }
    float4 b4a = *(const float4*)(bias + tx*8);
    float4 b4b = *(const float4*)(bias + tx*8 + 4);
    #pragma unroll
    for (int p = 0; p < 4; p++){
        #pragma unroll
        for (int j = 0; j < 2; j++){
            int row = bm0 + ty*8 + 2*p + j;
            if (row >= n) continue;
            float vals[8];
            #pragma unroll
            for (int c = 0; c < 8; c++){
                unsigned long long u = acc[p][c];
                vals[c] = j ? __uint_as_float((unsigned)(u >> 32))
                            : __uint_as_float((unsigned)u);
            }
            float dg = deg[row];
            float sc = fill / (dg + fill);
            float4 lo = make_float4(vals[0], vals[1], vals[2], vals[3]);
            float4 hi = make_float4(vals[4], vals[5], vals[6], vals[7]);
            *(float4*)(C + (size_t)row * 128 + tx*8)     = lo;
            *(float4*)(C + (size_t)row * 128 + tx*8 + 4) = hi;
            float4 o1 = make_float4(sc*vals[0] + b4a.x, sc*vals[1] + b4a.y,
                                    sc*vals[2] + b4a.z, sc*vals[3] + b4a.w);
            float4 o2 = make_float4(sc*vals[4] + b4b.x, sc*vals[5] + b4b.y,
                                    sc*vals[6] + b4b.z, sc*vals[7] + b4b.w);
            *(float4*)(out + (size_t)row * 128 + tx*8)     = o1;
            *(float4*)(out + (size_t)row * 128 + tx*8 + 4) = o2;
        }
    }
}

// ------------------------- CSR gather (+ optional fused score) -------------------------
__global__ void k_gather(const int* __restrict__ rp, const int* __restrict__ csrc,
                         const float* __restrict__ cc, const float* __restrict__ C,
                         float* __restrict__ out, int n, const float* __restrict__ p){
    int wid = (blockIdx.x * blockDim.x + threadIdx.x) >> 5;
    int lane = threadIdx.x & 31;
    if (wid >= n) return;
    int beg = rp[wid], end = rp[wid + 1];
    float4 acc = make_float4(0.f, 0.f, 0.f, 0.f);
    int e = beg;
    for (; e + 1 < end; e += 2){
        int s0 = csrc[e], s1 = csrc[e+1];
        float c0 = cc[e], c1 = cc[e+1];
        float4 v0 = *(const float4*)(C + (size_t)s0 * 128 + lane * 4);
        float4 v1 = *(const float4*)(C + (size_t)s1 * 128 + lane * 4);
        acc.x += c0*v0.x + c1*v1.x;
        acc.y += c0*v0.y + c1*v1.y;
        acc.z += c0*v0.z + c1*v1.z;
        acc.w += c0*v0.w + c1*v1.w;
    }
    if (e < end){
        int s0 = csrc[e];
        float c0 = cc[e];
        float4 v0 = *(const float4*)(C + (size_t)s0 * 128 + lane * 4);
        acc.x += c0*v0.x; acc.y += c0*v0.y; acc.z += c0*v0.z; acc.w += c0*v0.w;
    }
    float4 o = *(float4*)(out + (size_t)wid * 128 + lane * 4);
    o.x += acc.x; o.y += acc.y; o.z += acc.z; o.w += acc.w;
    *(float4*)(out + (size_t)wid * 128 + lane * 4) = o;
    if (p){
        float4 pv = *(const float4*)(p + lane * 4);
        float4 hv = lrelu4(o);
        float d = hv.x*pv.x + hv.y*pv.y + hv.z*pv.z + hv.w*pv.w;
        float pp = pv.x*pv.x + pv.y*pv.y + pv.z*pv.z + pv.w*pv.w;
        #pragma unroll
        for (int off = 16; off > 0; off >>= 1){
            d  += __shfl_xor_sync(0xffffffffu, d, off);
            pp += __shfl_xor_sync(0xffffffffu, pp, off);
        }
        if (lane == 0){
            float v = tanhf(d / sqrtf(pp));
            g_s[wid] = v;
            g_u[wid] = fenc(v);
        }
    }
}

// ------------------------- single-launch 3-pass radix select -------------------------
__device__ __forceinline__ void warp_sel(const unsigned* A, int nbins, int k,
                                         unsigned* outBin, int* outKrem){
    int lane = threadIdx.x & 31;
    int chunk = nbins >> 5;
    int base = nbins - 1 - lane * chunk;
    unsigned cnt = 0;
    for (int j = 0; j < chunk; j++) cnt += A[base - j];
    unsigned pre = cnt;
    #pragma unroll
    for (int off = 1; off < 32; off <<= 1){
        unsigned t = __shfl_up_sync(0xffffffffu, pre, off);
        if (lane >= off) pre += t;
    }
    pre -= cnt;
    bool sel = (pre < (unsigned)k) && ((unsigned)k <= pre + cnt);
    unsigned m = __ballot_sync(0xffffffffu, sel);
    int L = __ffs(m) - 1;
    unsigned bin = 0; int krem = 0;
    if (lane == L){
        unsigned run = pre;
        for (int j = 0; j < chunk; j++){
            int b = base - j;
            unsigned c = A[b];
            if (run + c >= (unsigned)k){ bin = (unsigned)b; krem = k - (int)run; break; }
            run += c;
        }
    }
    bin  = __shfl_sync(0xffffffffu, bin, L);
    krem = __shfl_sync(0xffffffffu, krem, L);
    *outBin = bin; *outKrem = krem;
}

__global__ void __launch_bounds__(512) k_histsel(int n, int k){
    __shared__ unsigned sh[2048];
    __shared__ int amLast;
    __shared__ unsigned sPref;
    __shared__ int sKrem;
    int tid = threadIdx.x;
    for (int j = tid; j < 2048; j += 512) sh[j] = 0u;
    __syncthreads();
    for (int i = blockIdx.x * 512 + tid; i < n; i += gridDim.x * 512)
        atomicAdd(&sh[g_u[i] >> 21], 1u);
    __syncthreads();
    for (int j = tid; j < 2048; j += 512){
        unsigned c = sh[j];
        if (c) atomicAdd(&g_hist[j], c);
    }
    __threadfence();
    __syncthreads();
    if (tid == 0)
        amLast = (atomicAdd(&g_done, 1u) == (unsigned)(gridDim.x - 1));
    __syncthreads();
    if (!amLast) return;

    // pass 0 select (from global hist)
    if (tid < 32){
        unsigned b; int kr;
        warp_sel(g_hist, 2048, k, &b, &kr);
        if (tid == 0){ sPref = b; sKrem = kr; }
    }
    __syncthreads();
    // pass 1
    for (int j = tid; j < 2048; j += 512){ sh[j] = 0u; g_hist[j] = 0u; }
    __syncthreads();
    unsigned p0 = sPref;
    for (int i = tid; i < n; i += 512){
        unsigned ui = g_u[i];
        if ((ui >> 21) == p0) atomicAdd(&sh[(ui >> 10) & 2047u], 1u);
    }
    __syncthreads();
    if (tid < 32){
        unsigned b; int kr;
        warp_sel(sh, 2048, sKrem, &b, &kr);
        if (tid == 0){ sPref = (p0 << 11) | b; sKrem = kr; }
    }
    __syncthreads();
    // pass 2
    for (int j = tid; j < 1024; j += 512) sh[j] = 0u;
    __syncthreads();
    unsigned p1 = sPref;
    for (int i = tid; i < n; i += 512){
        unsigned ui = g_u[i];
        if ((ui >> 10) == p1) atomicAdd(&sh[ui & 1023u], 1u);
    }
    __syncthreads();
    if (tid < 32){
        unsigned b; int kr;
        warp_sel(sh, 1024, sKrem, &b, &kr);
        if (tid == 0){
            g_thr = (p1 << 10) | b;
            g_T = kr;
            g_pcnt = 0; g_eqcnt = 0;
            g_done = 0u;
        }
    }
}

// ------------------------- partition -------------------------
__global__ void k_partition(int n, int k, int* __restrict__ perm, int* __restrict__ pos,
                            float* __restrict__ degn, int lvl){
    int i = blockIdx.x * blockDim.x + threadIdx.x;
    if (i == 0) g_ecnt[lvl] = 0;
    if (i < k){ degn[i] = 0.f; g_cnt[i] = 0; }
    if (i >= n) return;
    unsigned ui = g_u[i], ut = g_thr;
    int p = -1;
    if (ui > ut) p = atomicAdd(&g_pcnt, 1);
    else if (ui == ut){
        int t = atomicAdd(&g_eqcnt, 1);
        if (t < g_T) p = atomicAdd(&g_pcnt, 1);
    }
    pos[i] = p;
    if (p >= 0) perm[p] = i;
}

// compact valid edges + child degree + child counts
__global__ void k_relabel(const int* __restrict__ s, const int* __restrict__ d,
                          const float* __restrict__ w, const int* __restrict__ pos,
                          int* __restrict__ ns, int* __restrict__ nd, float* __restrict__ nw,
                          float* __restrict__ degn, int lvl,
                          int fixedcnt, const int* __restrict__ dyncnt){
    int cnt = dyncnt ? *dyncnt : fixedcnt;
    for (int e = blockIdx.x * blockDim.x + threadIdx.x; e < cnt;
         e += gridDim.x * blockDim.x){
        int a = pos[s[e]], b = pos[d[e]];
        if (a >= 0 && b >= 0){
            int j = atomicAdd(&g_ecnt[lvl], 1);
            float we = w[e];
            ns[j] = a; nd[j] = b; nw[j] = we;
            atomicAdd(&degn[b], we);
            atomicAdd(&g_cnt[b], 1);
        }
    }
}

// ------------------------- readout -------------------------
__global__ void k_colsum(const float* __restrict__ h, int n){
    int d = threadIdx.x;
    int r0 = blockIdx.x * 256;
    int rend = min(r0 + 256, n);
    float acc = 0.f;
    for (int r = r0; r < rend; r++) acc += h[(size_t)r * 128 + d];
    atomicAdd(&g_gsum[d], acc);
}

__global__ void k_final(const float* __restrict__ Wr, const float* __restrict__ br,
                        const float* __restrict__ gr, const float* __restrict__ brn,
                        float* __restrict__ out, int osz){
    __shared__ float gs[HD];
    int t = threadIdx.x;
    gs[t] = g_gsum[t];
    __syncthreads();
    float acc = br[t];
    for (int d2 = 0; d2 < HD; d2++) acc += gs[d2] * Wr[d2 * HD + t];
    float r = acc * (gr[t] * BNS) + brn[t];
    if (t < osz) out[t] = r;
}

// ------------------------- host orchestration -------------------------
extern "C" void kernel_launch(void* const* d_in, const int* in_sizes, int n_in,
                              void* d_out, int out_size){
    const float* x   = (const float*)d_in[0];
    const int*   ei  = (const int*)d_in[1];
    const float* ea  = (const float*)d_in[2];
    const float* Wew = (const float*)d_in[3];
    const float* Web = (const float*)d_in[4];
    const float* Wd  = (const float*)d_in[5];
    const float* bd  = (const float*)d_in[6];
    const float* Wp  = (const float*)d_in[7];
    const float* Wu  = (const float*)d_in[8];
    const float* bu  = (const float*)d_in[9];
    const float* gn  = (const float*)d_in[10];
    const float* bnm = (const float*)d_in[11];
    const float* Wr  = (const float*)d_in[12];
    const float* br  = (const float*)d_in[13];
    const float* gr  = (const float*)d_in[14];
    const float* brn = (const float*)d_in[15];
    float* out = (float*)d_out;

    void *pH0,*pH1,*pH2,*pW,*pO,*pB,*pEw0,*pSrc,*pDst,*pEwl;
    void *pCs,*pC1,*pC2,*pR0,*pR1,*pR2,*pR3;
    void *pP1,*pP2,*pP3,*pQ1,*pQ2,*pQ3,*pD0,*pD1,*pD2,*pD3,*pGs,*pEc;
    cudaGetSymbolAddress(&pH0, g_h0);  cudaGetSymbolAddress(&pH1, g_h1);
    cudaGetSymbolAddress(&pH2, g_h2);  cudaGetSymbolAddress(&pW, g_w);
    cudaGetSymbolAddress(&pO, g_o);    cudaGetSymbolAddress(&pB, g_bb);
    cudaGetSymbolAddress(&pEw0, g_ew0);
    cudaGetSymbolAddress(&pSrc, g_srcl); cudaGetSymbolAddress(&pDst, g_dstl);
    cudaGetSymbolAddress(&pEwl, g_ewl);
    cudaGetSymbolAddress(&pCs, g_csrc); cudaGetSymbolAddress(&pC1, g_cc1);
    cudaGetSymbolAddress(&pC2, g_cc2);
    cudaGetSymbolAddress(&pR0, g_rp0); cudaGetSymbolAddress(&pR1, g_rp1);
    cudaGetSymbolAddress(&pR2, g_rp2); cudaGetSymbolAddress(&pR3, g_rp3);
    cudaGetSymbolAddress(&pP1, g_perm1); cudaGetSymbolAddress(&pP2, g_perm2);
    cudaGetSymbolAddress(&pP3, g_perm3);
    cudaGetSymbolAddress(&pQ1, g_pos1);  cudaGetSymbolAddress(&pQ2, g_pos2);
    cudaGetSymbolAddress(&pQ3, g_pos3);
    cudaGetSymbolAddress(&pD0, g_deg0);  cudaGetSymbolAddress(&pD1, g_deg1);
    cudaGetSymbolAddress(&pD2, g_deg2);  cudaGetSymbolAddress(&pD3, g_deg3);
    cudaGetSymbolAddress(&pGs, g_gsum);  cudaGetSymbolAddress(&pEc, g_ecnt);

    float* h0=(float*)pH0; float* h1=(float*)pH1; float* h2=(float*)pH2;
    float* wb=(float*)pW;  float* o =(float*)pO;  float* b =(float*)pB;
    float* ew0=(float*)pEw0;
    int* srcB=(int*)pSrc; int* dstB=(int*)pDst; float* ewB=(float*)pEwl;
    int* src1=srcB;        int* dst1=dstB;        float* ew1=ewB;
    int* src2=srcB+EE;     int* dst2=dstB+EE;     float* ew2=ewB+EE;
    int* src3=srcB+2*EE;   int* dst3=dstB+2*EE;   float* ew3=ewB+2*EE;
    int* csrc=(int*)pCs; float* cc1=(float*)pC1; float* cc2=(float*)pC2;
    int* rp0=(int*)pR0; int* rp1=(int*)pR1; int* rp2=(int*)pR2; int* rp3=(int*)pR3;
    int* perm1=(int*)pP1;  int* perm2=(int*)pP2;  int* perm3=(int*)pP3;
    int* pos1=(int*)pQ1;   int* pos2=(int*)pQ2;   int* pos3=(int*)pQ3;
    float* deg0=(float*)pD0; float* deg1=(float*)pD1;
    float* deg2=(float*)pD2; float* deg3=(float*)pD3;
    int* ecnt=(int*)pEc;
    const int* src0 = ei;
    const int* dst0 = ei + EE;
    const float* NUF = nullptr;
    const int* NUI = nullptr;

    // ---- setup ----
    k_init<<<cdiv(NN,256),256>>>();
    k_ew<<<cdiv(EE,256),256>>>(ea, Wew, Web);
    k_ewfin<<<cdiv(EE,256),256>>>(dst0);
    k_scan<<<1,1024>>>(deg0, NN, rp0);
    k_fill<<<2048,256>>>(src0, dst0, ew0, EE, nullptr, csrc, cc1, cc2);

    // ---- GCN0 (BN fused) -> h0 ----
    k_mm<<<cdiv(NN,128),256>>>(x, Wd, wb, h0, bd, gn, bnm,
                               NUI, NUI, NUF, 0, deg0, 1.f, NN);
    k_gather<<<cdiv(NN*32,256),256>>>(rp0, csrc, cc1, wb, h0, NN, Wp);

    // ---- pool1 + GCN1 -> h1 ----
    k_histsel<<<148,512>>>(NN, L1N);
    k_partition<<<cdiv(NN,256),256>>>(NN, L1N, perm1, pos1, deg1, 0);
    k_relabel<<<2048,256>>>(src0, dst0, ew0, pos1, src1, dst1, ew1, deg1, 0, EE, nullptr);
    k_scan<<<1,1024>>>(deg1, L1N, rp1);
    k_fill<<<2048,256>>>(src1, dst1, ew1, 0, ecnt+0, csrc+EE, cc1+EE, cc2+EE);
    k_mm<<<cdiv(L1N,128),256>>>(h0, Wd+HD*HD, wb, h1, bd+HD, gn+HD, bnm+HD,
                                perm1, NUI, NUF, 0, deg1, 1.f, L1N);
    k_gather<<<cdiv(L1N*32,256),256>>>(rp1, csrc+EE, cc1+EE, wb, h1, L1N, Wp+HD);

    // ---- pool2 + GCN2 -> h2 ----
    k_histsel<<<148,512>>>(L1N, L2N);
    k_partition<<<cdiv(L1N,256),256>>>(L1N, L2N, perm2, pos2, deg2, 1);
    k_relabel<<<2048,256>>>(src1, dst1, ew1, pos2, src2, dst2, ew2, deg2, 1, 0, ecnt+0);
    k_scan<<<1,1024>>>(deg2, L2N, rp2);
    k_fill<<<2048,256>>>(src2, dst2, ew2, 0, ecnt+1, csrc+2*EE, cc1+2*EE, cc2+2*EE);
    k_mm<<<cdiv(L2N,128),256>>>(h1, Wd+2*HD*HD, wb, h2, bd+2*HD, gn+2*HD, bnm+2*HD,
                                perm2, NUI, NUF, 0, deg2, 1.f, L2N);
    k_gather<<<cdiv(L2N*32,256),256>>>(rp2, csrc+2*EE, cc1+2*EE, wb, h2, L2N, Wp+2*HD);

    // ---- pool3 + GCN3 -> o (bottom) ----
    k_histsel<<<148,512>>>(L2N, L3N);
    k_partition<<<cdiv(L2N,256),256>>>(L2N, L3N, perm3, pos3, deg3, 2);
    k_relabel<<<2048,256>>>(src2, dst2, ew2, pos3, src3, dst3, ew3, deg3, 2, 0, ecnt+1);
    k_scan<<<1,1024>>>(deg3, L3N, rp3);
    k_fill<<<2048,256>>>(src3, dst3, ew3, 0, ecnt+2, csrc+3*EE, cc1+3*EE, cc2+3*EE);
    k_mm<<<cdiv(L3N,128),256>>>(h2, Wd+3*HD*HD, wb, o, bd+3*HD, gn+3*HD, bnm+3*HD,
                                perm3, NUI, NUF, 0, deg3, 1.f, L3N);
    k_gather<<<cdiv(L3N*32,256),256>>>(rp3, csrc+3*EE, cc1+3*EE, wb, o, L3N, NUF);

    // ---- up 0 (n=12500): res=h2, unpool o (no lrelu on u) -> b ----
    k_mm<<<cdiv(L2N,128),256>>>(h2, Wu, wb, b, bu, NUF, NUF,
                                NUI, pos3, o, 0, deg2, 2.f, L2N);
    k_gather<<<cdiv(L2N*32,256),256>>>(rp2, csrc+2*EE, cc2+2*EE, wb, b, L2N, NUF);

    // ---- up 1 (n=25000): res=h1, unpool lrelu(b) -> o ----
    k_mm<<<cdiv(L1N,128),256>>>(h1, Wu+HD*HD, wb, o, bu+HD, NUF, NUF,
                                NUI, pos2, b, 1, deg1, 2.f, L1N);
    k_gather<<<cdiv(L1N*32,256),256>>>(rp1, csrc+EE, cc2+EE, wb, o, L1N, NUF);

    // ---- up 2 (n=50000): res=h0, unpool lrelu(o) -> b ----
    k_mm<<<cdiv(NN,128),256>>>(h0, Wu+2*HD*HD, wb, b, bu+2*HD, NUF, NUF,
                               NUI, pos1, o, 1, deg0, 2.f, NN);
    k_gather<<<cdiv(NN*32,256),256>>>(rp0, csrc, cc2, wb, b, NN, NUF);

    // ---- readout ----
    cudaMemsetAsync(pGs, 0, HD * sizeof(float));
    k_colsum<<<cdiv(NN,256),128>>>(b, NN);
    k_final<<<1,128>>>(Wr, br, gr, brn, out, out_size);
}